// round 1
// baseline (speedup 1.0000x reference)
#include <cuda_runtime.h>
#include <math.h>

// Problem shape (fixed)
#define B_   8
#define N_   1024
#define D_   768
#define H_   12
#define HD_  64
#define M_TOT (B_ * N_)   // 8192

// Scratch buffers (static device globals: allowed; cudaMalloc is not)
__device__ float g_Q [B_ * N_ * D_];
__device__ float g_K [B_ * N_ * D_];
__device__ float g_V [B_ * N_ * D_];
__device__ float g_AO[B_ * N_ * D_];

// ---------------------------------------------------------------------------
// SGEMM: C[M,N] = A[M,K] @ W[N,K]^T + bias[N]
// Classic 128x128x16 tile, 256 threads, 8x8 per-thread micro-tile.
// Both A and W are K-major row-major, so both load paths are identical.
// ---------------------------------------------------------------------------
#define BM 128
#define BN 128
#define BK 16
#define TM 8
#define TN 8

__global__ __launch_bounds__(256) void sgemm_bias(
    const float* __restrict__ A, const float* __restrict__ W,
    const float* __restrict__ bias, float* __restrict__ C,
    int M, int N, int K)
{
    __shared__ float As[BK][BM];
    __shared__ float Ws[BK][BN];

    const int t  = threadIdx.x;
    const int bm = blockIdx.y * BM;
    const int bn = blockIdx.x * BN;
    const int tx = t & 15;          // 0..15  (N direction)
    const int ty = t >> 4;          // 0..15  (M direction)

    float acc[TM][TN];
    #pragma unroll
    for (int i = 0; i < TM; i++)
        #pragma unroll
        for (int j = 0; j < TN; j++)
            acc[i][j] = 0.f;

    for (int k0 = 0; k0 < K; k0 += BK) {
        // Load tiles: 128 rows x 16 k, as float4 along K, stored transposed.
        #pragma unroll
        for (int r = 0; r < 2; r++) {
            int i   = t + r * 256;     // 0..511
            int row = i >> 2;          // 0..127
            int kc  = (i & 3) * 4;     // 0,4,8,12
            float4 a4 = *reinterpret_cast<const float4*>(
                A + (size_t)(bm + row) * K + k0 + kc);
            As[kc + 0][row] = a4.x; As[kc + 1][row] = a4.y;
            As[kc + 2][row] = a4.z; As[kc + 3][row] = a4.w;
            float4 w4 = *reinterpret_cast<const float4*>(
                W + (size_t)(bn + row) * K + k0 + kc);
            Ws[kc + 0][row] = w4.x; Ws[kc + 1][row] = w4.y;
            Ws[kc + 2][row] = w4.z; Ws[kc + 3][row] = w4.w;
        }
        __syncthreads();

        #pragma unroll
        for (int kk = 0; kk < BK; kk++) {
            float a[TM], b[TN];
            #pragma unroll
            for (int i = 0; i < TM; i += 4) {
                float4 f = *reinterpret_cast<const float4*>(&As[kk][ty * TM + i]);
                a[i] = f.x; a[i + 1] = f.y; a[i + 2] = f.z; a[i + 3] = f.w;
            }
            #pragma unroll
            for (int j = 0; j < TN; j += 4) {
                float4 f = *reinterpret_cast<const float4*>(&Ws[kk][tx * TN + j]);
                b[j] = f.x; b[j + 1] = f.y; b[j + 2] = f.z; b[j + 3] = f.w;
            }
            #pragma unroll
            for (int i = 0; i < TM; i++)
                #pragma unroll
                for (int j = 0; j < TN; j++)
                    acc[i][j] += a[i] * b[j];
        }
        __syncthreads();
    }

    // Epilogue: add bias, vectorized store.
    #pragma unroll
    for (int i = 0; i < TM; i++) {
        int rr = bm + ty * TM + i;
        #pragma unroll
        for (int j4 = 0; j4 < TN / 4; j4++) {
            int cc = bn + tx * TN + j4 * 4;
            float4 f;
            f.x = acc[i][j4 * 4 + 0] + bias[cc + 0];
            f.y = acc[i][j4 * 4 + 1] + bias[cc + 1];
            f.z = acc[i][j4 * 4 + 2] + bias[cc + 2];
            f.w = acc[i][j4 * 4 + 3] + bias[cc + 3];
            *reinterpret_cast<float4*>(C + (size_t)rr * N + cc) = f;
        }
    }
}

// ---------------------------------------------------------------------------
// Flash-style attention. One thread owns one query row (q + o live in regs).
// Block = 128 threads = 128 query rows; grid = (N/128, B*H).
// K/V staged in smem in 16-key tiles; all threads read the same smem word in
// lockstep -> broadcast, conflict-free. Online softmax (tile-wise rescale).
// Scale uses EMBED dim (768), matching the reference.
// ---------------------------------------------------------------------------
#define AT_ROWS 128
#define AT_BC   16

__global__ __launch_bounds__(AT_ROWS) void attn_kernel(
    const float* __restrict__ Q, const float* __restrict__ K,
    const float* __restrict__ V, float* __restrict__ O)
{
    __shared__ float Ks[AT_BC][HD_];
    __shared__ float Vs[AT_BC][HD_];

    const int t   = threadIdx.x;
    const int bh  = blockIdx.y;
    const int b   = bh / H_;
    const int h   = bh % H_;
    const int row = blockIdx.x * AT_ROWS + t;
    const float scale = 0.03608439182435161f;   // 768^-0.5

    float q[HD_];
    const float* qp = Q + ((size_t)(b * N_ + row)) * D_ + h * HD_;
    #pragma unroll
    for (int d4 = 0; d4 < HD_ / 4; d4++) {
        float4 f = reinterpret_cast<const float4*>(qp)[d4];
        q[4 * d4 + 0] = f.x; q[4 * d4 + 1] = f.y;
        q[4 * d4 + 2] = f.z; q[4 * d4 + 3] = f.w;
    }

    float o[HD_];
    #pragma unroll
    for (int d = 0; d < HD_; d++) o[d] = 0.f;
    float m = -1e30f, l = 0.f;

    const float* kbase = K + ((size_t)b * N_) * D_ + h * HD_;
    const float* vbase = V + ((size_t)b * N_) * D_ + h * HD_;

    for (int j0 = 0; j0 < N_; j0 += AT_BC) {
        __syncthreads();    // previous tile fully consumed
        #pragma unroll
        for (int r = 0; r < 2; r++) {
            int i  = t + r * AT_ROWS;   // 0..255
            int kr = i >> 4;            // 0..15
            int kc = (i & 15) * 4;      // 0..60
            *reinterpret_cast<float4*>(&Ks[kr][kc]) =
                *reinterpret_cast<const float4*>(kbase + (size_t)(j0 + kr) * D_ + kc);
            *reinterpret_cast<float4*>(&Vs[kr][kc]) =
                *reinterpret_cast<const float4*>(vbase + (size_t)(j0 + kr) * D_ + kc);
        }
        __syncthreads();

        // S tile: s[j] = (q . k_j) * scale
        float s[AT_BC];
        #pragma unroll
        for (int j = 0; j < AT_BC; j++) {
            float acc = 0.f;
            #pragma unroll
            for (int d4 = 0; d4 < HD_ / 4; d4++) {
                float4 kf = *reinterpret_cast<const float4*>(&Ks[j][4 * d4]);
                acc += q[4 * d4 + 0] * kf.x + q[4 * d4 + 1] * kf.y
                     + q[4 * d4 + 2] * kf.z + q[4 * d4 + 3] * kf.w;
            }
            s[j] = acc * scale;
        }

        // Online softmax update
        float tm = s[0];
        #pragma unroll
        for (int j = 1; j < AT_BC; j++) tm = fmaxf(tm, s[j]);
        float mnew = fmaxf(m, tm);
        float c    = __expf(m - mnew);
        float ps   = 0.f;
        #pragma unroll
        for (int j = 0; j < AT_BC; j++) { s[j] = __expf(s[j] - mnew); ps += s[j]; }
        l = l * c + ps;
        m = mnew;

        #pragma unroll
        for (int d = 0; d < HD_; d++) o[d] *= c;

        // O += P . V
        #pragma unroll
        for (int j = 0; j < AT_BC; j++) {
            float p = s[j];
            #pragma unroll
            for (int d4 = 0; d4 < HD_ / 4; d4++) {
                float4 vf = *reinterpret_cast<const float4*>(&Vs[j][4 * d4]);
                o[4 * d4 + 0] += p * vf.x; o[4 * d4 + 1] += p * vf.y;
                o[4 * d4 + 2] += p * vf.z; o[4 * d4 + 3] += p * vf.w;
            }
        }
    }

    const float inv = 1.f / l;
    float* op = O + ((size_t)(b * N_ + row)) * D_ + h * HD_;
    #pragma unroll
    for (int d4 = 0; d4 < HD_ / 4; d4++) {
        float4 f;
        f.x = o[4 * d4 + 0] * inv; f.y = o[4 * d4 + 1] * inv;
        f.z = o[4 * d4 + 2] * inv; f.w = o[4 * d4 + 3] * inv;
        reinterpret_cast<float4*>(op)[d4] = f;
    }
}

// ---------------------------------------------------------------------------
// Launch
// ---------------------------------------------------------------------------
extern "C" void kernel_launch(void* const* d_in, const int* in_sizes, int n_in,
                              void* d_out, int out_size)
{
    const float* x  = (const float*)d_in[0];
    const float* Wq = (const float*)d_in[1];
    const float* bq = (const float*)d_in[2];
    const float* Wk = (const float*)d_in[3];
    const float* bk = (const float*)d_in[4];
    const float* Wv = (const float*)d_in[5];
    const float* bv = (const float*)d_in[6];
    const float* Wo = (const float*)d_in[7];
    const float* bo = (const float*)d_in[8];
    float* out = (float*)d_out;

    float *Qp, *Kp, *Vp, *AOp;
    cudaGetSymbolAddress((void**)&Qp,  g_Q);
    cudaGetSymbolAddress((void**)&Kp,  g_K);
    cudaGetSymbolAddress((void**)&Vp,  g_V);
    cudaGetSymbolAddress((void**)&AOp, g_AO);

    dim3 gemm_grid(D_ / BN, M_TOT / BM);   // (6, 64)
    sgemm_bias<<<gemm_grid, 256>>>(x, Wq, bq, Qp, M_TOT, D_, D_);
    sgemm_bias<<<gemm_grid, 256>>>(x, Wk, bk, Kp, M_TOT, D_, D_);
    sgemm_bias<<<gemm_grid, 256>>>(x, Wv, bv, Vp, M_TOT, D_, D_);

    dim3 attn_grid(N_ / AT_ROWS, B_ * H_); // (8, 96)
    attn_kernel<<<attn_grid, AT_ROWS>>>(Qp, Kp, Vp, AOp);

    sgemm_bias<<<gemm_grid, 256>>>(AOp, Wo, bo, out, M_TOT, D_, D_);
}